// round 15
// baseline (speedup 1.0000x reference)
#include <cuda_runtime.h>

#define BATCH   128
#define LSIG    128000
#define NFFT    1024
#define HOP     320
#define NMELS   128
#define NFRAMES 401
#define NFREQ   513
#define MAXW    28
#define PI_D    3.14159265358979323846

// ---------------- device globals (no allocations allowed) -------------------
__device__ float2 g_win2[512];                 // (w[2n], w[2n+1]) interleaved hann
__device__ float2 g_tw[512];                   // W_1024^k
__device__ float2 g_tw512[512];                // W_512^k (full range)
__device__ int    g_mlo[NMELS];
__device__ int    g_mlen[NMELS];
__device__ float  g_fbw[MAXW][NMELS];          // zero-padded rows
__device__ float  g_mel[BATCH * NFRAMES * NMELS];

// ---------------- complex helpers -------------------------------------------
__device__ __forceinline__ float2 cadd(float2 a, float2 b){return make_float2(a.x+b.x, a.y+b.y);}
__device__ __forceinline__ float2 csub(float2 a, float2 b){return make_float2(a.x-b.x, a.y-b.y);}
__device__ __forceinline__ float2 cmul(float2 a, float2 b){return make_float2(a.x*b.x - a.y*b.y, a.x*b.y + a.y*b.x);}

__device__ __forceinline__ void dft8(float2 v[8]) {
    const float C = 0.70710678118654752f;
    float2 s0 = cadd(v[0], v[4]), d0 = csub(v[0], v[4]);
    float2 s1 = cadd(v[2], v[6]), d1 = csub(v[2], v[6]);
    float2 s2 = cadd(v[1], v[5]), d2 = csub(v[1], v[5]);
    float2 s3 = cadd(v[3], v[7]), d3 = csub(v[3], v[7]);
    float2 e0 = cadd(s0, s1), e2 = csub(s0, s1);
    float2 nid1 = make_float2(d1.y, -d1.x);
    float2 e1 = cadd(d0, nid1), e3 = csub(d0, nid1);
    float2 o0 = cadd(s2, s3), o2 = csub(s2, s3);
    float2 nid3 = make_float2(d3.y, -d3.x);
    float2 o1 = cadd(d2, nid3), o3 = csub(d2, nid3);
    float2 t1 = make_float2(C*(o1.x + o1.y), C*(o1.y - o1.x));
    float2 t2 = make_float2(o2.y, -o2.x);
    float2 t3 = make_float2(C*(o3.y - o3.x), -C*(o3.x + o3.y));
    v[0] = cadd(e0, o0); v[4] = csub(e0, o0);
    v[1] = cadd(e1, t1); v[5] = csub(e1, t1);
    v[2] = cadd(e2, t2); v[6] = csub(e2, t2);
    v[3] = cadd(e3, t3); v[7] = csub(e3, t3);
}

#define PAD(i) ((i) + ((i) >> 3))

// ---------------- init: fully parallel, fp32 trig (measured good, R10) -------
__global__ void init_kernel() {
    const int bx = blockIdx.x, tid = threadIdx.x;

    if (bx < NMELS) {
        __shared__ double sf[3];
        __shared__ double si01, si12;
        __shared__ int s_lo, s_hi;
        if (tid == 0) { s_lo = 1 << 30; s_hi = -1; }
        if (tid < 3) {
            double mel_max = 2595.0 * log10(1.0 + 16000.0 / 700.0);
            sf[tid] = 700.0 * (exp10((mel_max * (double)(bx + tid) / 129.0) / 2595.0) - 1.0);
        }
        __syncthreads();
        if (tid == 0) { si01 = 1.0 / (sf[1] - sf[0]); si12 = 1.0 / (sf[2] - sf[1]); }
        __syncthreads();

        double wgt = -1.0;
        if (tid < NFREQ) {
            double freq = (double)tid * (16000.0 / 512.0);
            wgt = fmin((freq - sf[0]) * si01, (sf[2] - freq) * si12);
            if (wgt > 0.0) { atomicMin(&s_lo, tid); atomicMax(&s_hi, tid); }
        }
        __syncthreads();
        int lo = s_lo, hi = s_hi;
        int len = (hi < 0) ? 0 : (hi - lo + 1);
        if (len > MAXW) len = MAXW;
        if (tid == 0) { g_mlo[bx] = (hi < 0) ? 0 : lo; g_mlen[bx] = len; }
        if (wgt > 0.0) {
            int i = tid - lo;
            if (i >= 0 && i < MAXW) g_fbw[i][bx] = (float)wgt;
        }
        if (tid < MAXW && tid >= len) g_fbw[tid][bx] = 0.0f;
    } else {
        int i = (bx - NMELS) * 64 + tid;
        if (tid < 64 && i < 512) {
            float w0 = 0.5f * (1.0f - cospif((float)(2 * i)     * (1.0f / 512.0f)));
            float w1 = 0.5f * (1.0f - cospif((float)(2 * i + 1) * (1.0f / 512.0f)));
            g_win2[i] = make_float2(w0, w1);
            float s, c;
            sincospif((float)i * (-1.0f / 512.0f), &s, &c);    // W_1024^i
            g_tw[i] = make_float2(c, s);
            float s2, c2;
            sincospif((float)i * (-1.0f / 256.0f), &s2, &c2);  // W_512^i
            g_tw512[i] = make_float2(c2, s2);
        }
    }
}

// ---------------- mel spectrogram: warp/frame, PING-PONG low-register --------
// A->B->A double buffering: stage reads never alias stage writes, so each
// 32-point half runs with only v[8] live (#pragma unroll 1 keeps halves
// sequential). Low regs + 100% smem carveout -> ~6 CTAs = 24 warps/SM.
__global__ __launch_bounds__(128) void melspec_kernel(const float* __restrict__ x) {
    __shared__ float2 bufA[4][576];             // 18432 B
    __shared__ float2 bufB[4][576];             // 18432 B

    const int tid  = threadIdx.x;
    const int w    = tid >> 5;
    const int lane = tid & 31;

    int t = blockIdx.x * 4 + w;
    const bool valid = (t < NFRAMES);
    if (!valid) t = NFRAMES - 1;
    const int b = blockIdx.y;

    float2* __restrict__ A = bufA[w];
    float2* __restrict__ B = bufB[w];

    const float* __restrict__ xb = x + (long long)b * LSIG;
    const int base = t * HOP - 512;
    const bool fast = (base >= 0) && (base + NFFT <= LSIG);

    // ---- stage 0 fused with load: out[8vt+k] = DFT8_k * W512^{vt*k} -> A
    #pragma unroll 1
    for (int h = 0; h < 2; h++) {
        const int vt = lane + 32 * h;
        float2 v[8];
        if (fast) {
            const float2* __restrict__ x2 = (const float2*)(xb + base);
            #pragma unroll
            for (int j = 0; j < 8; j++) {
                int n = vt + 64 * j;
                float2 s  = x2[n];
                float2 wn = g_win2[n];
                v[j] = make_float2(s.x * wn.x, s.y * wn.y);
            }
        } else {
            #pragma unroll
            for (int j = 0; j < 8; j++) {
                int n  = vt + 64 * j;
                int p0 = base + 2 * n, p1 = p0 + 1;
                p0 = p0 < 0 ? -p0 : (p0 >= LSIG ? 2 * LSIG - 2 - p0 : p0);
                p1 = p1 < 0 ? -p1 : (p1 >= LSIG ? 2 * LSIG - 2 - p1 : p1);
                float2 wn = g_win2[n];
                v[j] = make_float2(xb[p0] * wn.x, xb[p1] * wn.y);
            }
        }
        dft8(v);
        #pragma unroll
        for (int k = 1; k < 8; k++) v[k] = cmul(v[k], __ldg(&g_tw512[vt * k]));
        #pragma unroll
        for (int k = 0; k < 8; k++) A[PAD(8 * vt + k)] = v[k];
    }
    __syncwarp();

    // ---- stage 1: A -> B, out[64p + q + 8k] = DFT8_k * W512^{8pk}
    #pragma unroll 1
    for (int h = 0; h < 2; h++) {
        const int vt = lane + 32 * h, p = vt >> 3, q = vt & 7;
        float2 v[8];
        #pragma unroll
        for (int j = 0; j < 8; j++) v[j] = A[PAD(vt + 64 * j)];
        dft8(v);
        #pragma unroll
        for (int k = 1; k < 8; k++) v[k] = cmul(v[k], __ldg(&g_tw512[8 * p * k]));
        #pragma unroll
        for (int k = 0; k < 8; k++) B[PAD(64 * p + q + 8 * k)] = v[k];
    }
    __syncwarp();

    // ---- stage 2: B -> A, out[vt + 64k] = DFT8_k (no twiddle)
    #pragma unroll 1
    for (int h = 0; h < 2; h++) {
        const int vt = lane + 32 * h;
        float2 v[8];
        #pragma unroll
        for (int j = 0; j < 8; j++) v[j] = B[PAD(vt + 64 * j)];
        dft8(v);
        #pragma unroll
        for (int k = 0; k < 8; k++) A[PAD(vt + 64 * k)] = v[k];
    }
    __syncwarp();

    // ---- unpack A -> compact mags in B (no aliasing, no register spike)
    //   X[k] = E + W*O, X[512-k] = conj(E - W*O); k=0 pair gives DC+Nyquist.
    float* mag = (float*)B;
    #pragma unroll 1
    for (int u = 0; u < 8; u++) {
        int k = lane + 32 * (u & 1) + 64 * (u >> 1);   // 0..255
        float2 Zk = A[PAD(k)];
        float2 Zr = A[PAD((512 - k) & 511)];
        float ex = 0.5f * (Zk.x + Zr.x), ey = 0.5f * (Zk.y - Zr.y);
        float ox = 0.5f * (Zk.y + Zr.y), oy = 0.5f * (Zr.x - Zk.x);
        float2 tw = __ldg(&g_tw[k]);
        float wox = ox * tw.x - oy * tw.y;
        float woy = ox * tw.y + oy * tw.x;
        float ax = ex + wox, ay = ey + woy;
        float bx2 = ex - wox, by2 = ey - woy;
        mag[k]       = sqrtf(ax * ax + ay * ay);
        mag[512 - k] = sqrtf(bx2 * bx2 + by2 * by2);   // k=0 -> Nyquist bin 512
    }
    if (lane == 0) {
        float2 Z = A[PAD(256)];
        mag[256] = sqrtf(Z.x * Z.x + Z.y * Z.y);
        mag[513] = 0.0f; mag[514] = 0.0f; mag[515] = 0.0f;
        mag[516] = 0.0f; mag[517] = 0.0f; mag[518] = 0.0f;
        mag[519] = 0.0f;                    // x4-unroll pad: no NaN from 0*garbage
    }
    __syncwarp();

    // ---- mel gather: unrolled x4, zero-padded weights (R9 exact)
    if (valid) {
        float* __restrict__ om = g_mel + ((long long)b * NFRAMES + t) * NMELS;
        #pragma unroll
        for (int g = 0; g < 4; g++) {
            int m    = lane + 32 * g;
            int lo   = g_mlo[m];
            int len4 = (g_mlen[m] + 3) & ~3;
            const float* __restrict__ wm = &g_fbw[0][m];
            const float* __restrict__ mg = &mag[lo];
            float a0 = 0.0f, a1 = 0.0f, a2 = 0.0f, a3 = 0.0f;
            for (int i = 0; i < len4; i += 4) {
                a0 += mg[i    ] * wm[(i    ) * NMELS];
                a1 += mg[i + 1] * wm[(i + 1) * NMELS];
                a2 += mg[i + 2] * wm[(i + 2) * NMELS];
                a3 += mg[i + 3] * wm[(i + 3) * NMELS];
            }
            om[m] = (a0 + a1) + (a2 + a3);
        }
    }
}

// ---------------- PCEN: 4-chunk parallel IIR (exact R9 champion) -------------
__global__ __launch_bounds__(512) void pcen_kernel(float* __restrict__ out) {
    const int b   = blockIdx.x;
    const int tid = threadIdx.x;
    const int c   = tid >> 7;          // chunk 0..3
    const int m   = tid & 127;         // mel

    const int t0 = c * 101;
    const int t1 = (c == 3) ? NFRAMES : t0 + 101;

    const float* __restrict__ mel = g_mel + (long long)b * NFRAMES * NMELS;
    float* __restrict__ obase = out + (long long)b * NMELS * NFRAMES;

    const float a1c = 0.975f, s0 = 0.025f;
    const float sqrt2 = 1.41421356237309515f;

    __shared__ float sA[4][NMELS];
    __shared__ float sB[4][NMELS];
    __shared__ float sMin[4][NMELS];

    if (c == 0) {
        float M = mel[m];
        for (int t = 1; t < 101; t++)
            M = fmaf(a1c, M, s0 * mel[t * NMELS + m]);
        sA[0][m] = 0.0f; sB[0][m] = M;
    } else {
        float B = 0.0f;
        for (int t = t0; t < t1; t++)
            B = fmaf(a1c, B, s0 * mel[t * NMELS + m]);
        sA[c][m] = __powf(a1c, (float)(t1 - t0));
        sB[c][m] = B;
    }
    __syncthreads();

    if (tid < NMELS) {
        float e0 = sB[0][tid];
        float e1 = fmaf(sA[1][tid], e0, sB[1][tid]);
        float e2 = fmaf(sA[2][tid], e1, sB[2][tid]);
        sMin[0][tid] = 0.0f;
        sMin[1][tid] = e0;
        sMin[2][tid] = e1;
        sMin[3][tid] = e2;
    }
    __syncthreads();

    float M = sMin[c][m];
    float sum = 0.0f, cs = 0.0f, sq = 0.0f, cq = 0.0f;
    for (int t = t0; t < t1; t++) {
        float xv = mel[t * NMELS + m];
        M = (c == 0 && t == 0) ? xv : fmaf(a1c, M, s0 * xv);
        float z = 1e-6f + M;
        float u = fmaf(xv, __powf(z, -0.98f), 2.0f);
        float p = u * rsqrtf(u) - sqrt2;
        obase[m * NFRAMES + t] = p;
        float y = p - cs, tn = sum + y; cs = (tn - sum) - y; sum = tn;
        float pp = p * p;
        float y2 = pp - cq, tq = sq + y2; cq = (tq - sq) - y2; sq = tq;
    }

    __shared__ double dsum[512];
    __shared__ double dsq[512];
    __shared__ float  s_mean, s_inv;
    dsum[tid] = (double)sum + (double)cs;
    dsq[tid]  = (double)sq  + (double)cq;
    __syncthreads();
    for (int o = 256; o > 0; o >>= 1) {
        if (tid < o) { dsum[tid] += dsum[tid + o]; dsq[tid] += dsq[tid + o]; }
        __syncthreads();
    }
    if (tid == 0) {
        const double n = (double)(NMELS * NFRAMES);
        double mean = dsum[0] / n;
        double var  = (dsq[0] - dsum[0] * dsum[0] / n) / (n - 1.0);
        if (var < 0.0) var = 0.0;
        s_mean = (float)mean;
        s_inv  = (float)(1.0 / (sqrt(var) + 1e-6));
    }
    __syncthreads();

    float mean = s_mean, inv = s_inv;
    float4* o4 = (float4*)obase;
    const int tot4 = NMELS * NFRAMES / 4;
    for (int i = tid; i < tot4; i += 512) {
        float4 v = o4[i];
        v.x = (v.x - mean) * inv;
        v.y = (v.y - mean) * inv;
        v.z = (v.z - mean) * inv;
        v.w = (v.w - mean) * inv;
        o4[i] = v;
    }
}

// ---------------- launch ------------------------------------------------------
extern "C" void kernel_launch(void* const* d_in, const int* in_sizes, int n_in,
                              void* d_out, int out_size) {
    const float* x = (const float*)d_in[0];
    float* out = (float*)d_out;

    // 100% smem carveout: with ~37 KB/CTA static smem this permits 6 CTAs/SM
    // (24 warps) once register pressure is low. Idempotent, capture-legal.
    static int carveout_set = 0;
    if (!carveout_set) {
        cudaFuncSetAttribute(melspec_kernel,
                             cudaFuncAttributePreferredSharedMemoryCarveout, 100);
        carveout_set = 1;
    }

    init_kernel<<<NMELS + 8, 544>>>();
    melspec_kernel<<<dim3((NFRAMES + 3) / 4, BATCH), 128>>>(x);
    pcen_kernel<<<BATCH, 512>>>(out);
}

// round 16
// speedup vs baseline: 1.1565x; 1.1565x over previous
#include <cuda_runtime.h>

#define BATCH   128
#define LSIG    128000
#define NFFT    1024
#define HOP     320
#define NMELS   128
#define NFRAMES 401
#define NFREQ   513
#define MAXW    28
#define PI_D    3.14159265358979323846

// ---------------- device globals (no allocations allowed) -------------------
__device__ float2 g_win2[512];                 // (w[2n], w[2n+1]) interleaved hann
__device__ float2 g_tw[512];                   // W_1024^k
__device__ float2 g_tw512[512];                // W_512^k (full range)
__device__ int    g_mlo[NMELS];
__device__ int    g_mlen[NMELS];
__device__ float  g_fbw[MAXW][NMELS];          // zero-padded rows
__device__ float  g_mel[BATCH * NFRAMES * NMELS];

// ---------------- complex helpers -------------------------------------------
__device__ __forceinline__ float2 cadd(float2 a, float2 b){return make_float2(a.x+b.x, a.y+b.y);}
__device__ __forceinline__ float2 csub(float2 a, float2 b){return make_float2(a.x-b.x, a.y-b.y);}
__device__ __forceinline__ float2 cmul(float2 a, float2 b){return make_float2(a.x*b.x - a.y*b.y, a.x*b.y + a.y*b.x);}

// fast magnitude: |z| = u * rsqrt(u), u = re^2+im^2 (clamped vs 0*inf NaN)
__device__ __forceinline__ float fmag(float re, float im) {
    float u = fmaf(re, re, im * im);
    u = fmaxf(u, 1e-30f);
    return u * rsqrtf(u);
}

__device__ __forceinline__ void dft8(float2 v[8]) {
    const float C = 0.70710678118654752f;
    float2 s0 = cadd(v[0], v[4]), d0 = csub(v[0], v[4]);
    float2 s1 = cadd(v[2], v[6]), d1 = csub(v[2], v[6]);
    float2 s2 = cadd(v[1], v[5]), d2 = csub(v[1], v[5]);
    float2 s3 = cadd(v[3], v[7]), d3 = csub(v[3], v[7]);
    float2 e0 = cadd(s0, s1), e2 = csub(s0, s1);
    float2 nid1 = make_float2(d1.y, -d1.x);
    float2 e1 = cadd(d0, nid1), e3 = csub(d0, nid1);
    float2 o0 = cadd(s2, s3), o2 = csub(s2, s3);
    float2 nid3 = make_float2(d3.y, -d3.x);
    float2 o1 = cadd(d2, nid3), o3 = csub(d2, nid3);
    float2 t1 = make_float2(C*(o1.x + o1.y), C*(o1.y - o1.x));
    float2 t2 = make_float2(o2.y, -o2.x);
    float2 t3 = make_float2(C*(o3.y - o3.x), -C*(o3.x + o3.y));
    v[0] = cadd(e0, o0); v[4] = csub(e0, o0);
    v[1] = cadd(e1, t1); v[5] = csub(e1, t1);
    v[2] = cadd(e2, t2); v[6] = csub(e2, t2);
    v[3] = cadd(e3, t3); v[7] = csub(e3, t3);
}

#define PAD(i) ((i) + ((i) >> 3))

// ---------------- init: fully parallel, fp32 trig (R10, measured -2.3us) -----
__global__ void init_kernel() {
    const int bx = blockIdx.x, tid = threadIdx.x;

    if (bx < NMELS) {
        __shared__ double sf[3];
        __shared__ double si01, si12;
        __shared__ int s_lo, s_hi;
        if (tid == 0) { s_lo = 1 << 30; s_hi = -1; }
        if (tid < 3) {
            double mel_max = 2595.0 * log10(1.0 + 16000.0 / 700.0);
            sf[tid] = 700.0 * (exp10((mel_max * (double)(bx + tid) / 129.0) / 2595.0) - 1.0);
        }
        __syncthreads();
        if (tid == 0) { si01 = 1.0 / (sf[1] - sf[0]); si12 = 1.0 / (sf[2] - sf[1]); }
        __syncthreads();

        double wgt = -1.0;
        if (tid < NFREQ) {
            double freq = (double)tid * (16000.0 / 512.0);
            wgt = fmin((freq - sf[0]) * si01, (sf[2] - freq) * si12);
            if (wgt > 0.0) { atomicMin(&s_lo, tid); atomicMax(&s_hi, tid); }
        }
        __syncthreads();
        int lo = s_lo, hi = s_hi;
        int len = (hi < 0) ? 0 : (hi - lo + 1);
        if (len > MAXW) len = MAXW;
        if (tid == 0) { g_mlo[bx] = (hi < 0) ? 0 : lo; g_mlen[bx] = len; }
        if (wgt > 0.0) {
            int i = tid - lo;
            if (i >= 0 && i < MAXW) g_fbw[i][bx] = (float)wgt;
        }
        if (tid < MAXW && tid >= len) g_fbw[tid][bx] = 0.0f;   // zero pad rows
    } else {
        int i = (bx - NMELS) * 64 + tid;
        if (tid < 64 && i < 512) {
            float w0 = 0.5f * (1.0f - cospif((float)(2 * i)     * (1.0f / 512.0f)));
            float w1 = 0.5f * (1.0f - cospif((float)(2 * i + 1) * (1.0f / 512.0f)));
            g_win2[i] = make_float2(w0, w1);
            float s, c;
            sincospif((float)i * (-1.0f / 512.0f), &s, &c);    // W_1024^i
            g_tw[i] = make_float2(c, s);
            float s2, c2;
            sincospif((float)i * (-1.0f / 256.0f), &s2, &c2);  // W_512^i
            g_tw512[i] = make_float2(c2, s2);
        }
    }
}

// ---------------- mel spectrogram: one warp per frame (R9 champion body) -----
__global__ __launch_bounds__(128) void melspec_kernel(const float* __restrict__ x) {
    __shared__ float2 buf[4][576];              // 18432 B (FFT + in-place mags)
    __shared__ float2 tws[512];                 //  4096 B, full W_512 table

    const int tid  = threadIdx.x;
    const int w    = tid >> 5;
    const int lane = tid & 31;

    #pragma unroll
    for (int r = 0; r < 4; r++) tws[tid + 128 * r] = g_tw512[tid + 128 * r];
    __syncthreads();

    int t = blockIdx.x * 4 + w;
    const bool valid = (t < NFRAMES);
    if (!valid) t = NFRAMES - 1;
    const int b = blockIdx.y;

    const float* __restrict__ xb = x + (long long)b * LSIG;
    const int base = t * HOP - 512;
    float2 v[2][8];
    if (base >= 0 && base + (NFFT - 1) < LSIG) {
        const float2* __restrict__ x2 = (const float2*)(xb + base);
        #pragma unroll
        for (int h = 0; h < 2; h++)
        #pragma unroll
        for (int j = 0; j < 8; j++) {
            int n = lane + 32 * h + 64 * j;
            float2 s  = x2[n];
            float2 wn = g_win2[n];
            v[h][j] = make_float2(s.x * wn.x, s.y * wn.y);
        }
    } else {
        #pragma unroll
        for (int h = 0; h < 2; h++)
        #pragma unroll
        for (int j = 0; j < 8; j++) {
            int n  = lane + 32 * h + 64 * j;
            int p0 = base + 2 * n, p1 = p0 + 1;
            p0 = p0 < 0 ? -p0 : (p0 >= LSIG ? 2 * LSIG - 2 - p0 : p0);
            p1 = p1 < 0 ? -p1 : (p1 >= LSIG ? 2 * LSIG - 2 - p1 : p1);
            float2 wn = g_win2[n];
            v[h][j] = make_float2(xb[p0] * wn.x, xb[p1] * wn.y);
        }
    }

    // stage 0: out[8*vt + k] = DFT8_k * W512^{vt*k}
    #pragma unroll
    for (int h = 0; h < 2; h++) {
        int vt = lane + 32 * h;
        dft8(v[h]);
        #pragma unroll
        for (int k = 1; k < 8; k++) v[h][k] = cmul(v[h][k], tws[vt * k]);
        #pragma unroll
        for (int k = 0; k < 8; k++) buf[w][PAD(8 * vt + k)] = v[h][k];
    }
    __syncwarp();

    // stage 1: out[64p + q + 8k] = DFT8_k * W512^{8pk}
    #pragma unroll
    for (int h = 0; h < 2; h++)
    #pragma unroll
    for (int j = 0; j < 8; j++)
        v[h][j] = buf[w][PAD(lane + 32 * h + 64 * j)];
    __syncwarp();
    #pragma unroll
    for (int h = 0; h < 2; h++) {
        int vt = lane + 32 * h, p = vt >> 3, q = vt & 7;
        dft8(v[h]);
        #pragma unroll
        for (int k = 1; k < 8; k++) v[h][k] = cmul(v[h][k], tws[8 * p * k]);
        #pragma unroll
        for (int k = 0; k < 8; k++) buf[w][PAD(64 * p + q + 8 * k)] = v[h][k];
    }
    __syncwarp();

    // stage 2: out[vt + 64k] = DFT8_k (no twiddle)
    #pragma unroll
    for (int h = 0; h < 2; h++)
    #pragma unroll
    for (int j = 0; j < 8; j++)
        v[h][j] = buf[w][PAD(lane + 32 * h + 64 * j)];
    __syncwarp();
    #pragma unroll
    for (int h = 0; h < 2; h++) {
        int vt = lane + 32 * h;
        dft8(v[h]);
        #pragma unroll
        for (int k = 0; k < 8; k++) buf[w][PAD(vt + 64 * k)] = v[h][k];
    }
    __syncwarp();

    // conjugate-pair unpack, in place (R9), fast magnitudes
    float2 zk[8], zr[8];
    #pragma unroll
    for (int u = 0; u < 8; u++) {
        int k = lane + 32 * (u & 1) + 64 * (u >> 1);   // 0..255
        zk[u] = buf[w][PAD(k)];
        zr[u] = buf[w][PAD((512 - k) & 511)];
    }
    float2 Z256;
    if (lane == 0) Z256 = buf[w][PAD(256)];
    __syncwarp();
    float* mag = (float*)buf[w];                // compact [0..519] floats
    #pragma unroll
    for (int u = 0; u < 8; u++) {
        int k = lane + 32 * (u & 1) + 64 * (u >> 1);
        float ex = 0.5f * (zk[u].x + zr[u].x), ey = 0.5f * (zk[u].y - zr[u].y);
        float ox = 0.5f * (zk[u].y + zr[u].y), oy = 0.5f * (zr[u].x - zk[u].x);
        float2 tw = __ldg(&g_tw[k]);
        float wox = ox * tw.x - oy * tw.y;
        float woy = ox * tw.y + oy * tw.x;
        mag[k]       = fmag(ex + wox, ey + woy);
        mag[512 - k] = fmag(ex - wox, ey - woy);       // k=0 -> Nyquist bin 512
    }
    if (lane == 0) {
        mag[256] = fmag(Z256.x, Z256.y);
        mag[513] = 0.0f; mag[514] = 0.0f; mag[515] = 0.0f;
        mag[516] = 0.0f; mag[517] = 0.0f; mag[518] = 0.0f;
        mag[519] = 0.0f;                    // x4-unroll pad: no NaN from 0*garbage
    }
    __syncwarp();

    // mel gather: unrolled x4, zero-padded weights (R9 exact)
    if (valid) {
        float* __restrict__ om = g_mel + ((long long)b * NFRAMES + t) * NMELS;
        #pragma unroll
        for (int g = 0; g < 4; g++) {
            int m    = lane + 32 * g;
            int lo   = g_mlo[m];
            int len4 = (g_mlen[m] + 3) & ~3;
            const float* __restrict__ wm = &g_fbw[0][m];
            const float* __restrict__ mg = &mag[lo];
            float a0 = 0.0f, a1 = 0.0f, a2 = 0.0f, a3 = 0.0f;
            for (int i = 0; i < len4; i += 4) {
                a0 += mg[i    ] * wm[(i    ) * NMELS];
                a1 += mg[i + 1] * wm[(i + 1) * NMELS];
                a2 += mg[i + 2] * wm[(i + 2) * NMELS];
                a3 += mg[i + 3] * wm[(i + 3) * NMELS];
            }
            om[m] = (a0 + a1) + (a2 + a3);
        }
    }
}

// ---------------- PCEN: 4-chunk parallel IIR (exact R9 champion) -------------
__global__ __launch_bounds__(512) void pcen_kernel(float* __restrict__ out) {
    const int b   = blockIdx.x;
    const int tid = threadIdx.x;
    const int c   = tid >> 7;          // chunk 0..3
    const int m   = tid & 127;         // mel

    const int t0 = c * 101;
    const int t1 = (c == 3) ? NFRAMES : t0 + 101;

    const float* __restrict__ mel = g_mel + (long long)b * NFRAMES * NMELS;
    float* __restrict__ obase = out + (long long)b * NMELS * NFRAMES;

    const float a1c = 0.975f, s0 = 0.025f;
    const float sqrt2 = 1.41421356237309515f;

    __shared__ float sA[4][NMELS];
    __shared__ float sB[4][NMELS];
    __shared__ float sMin[4][NMELS];

    if (c == 0) {
        float M = mel[m];
        for (int t = 1; t < 101; t++)
            M = fmaf(a1c, M, s0 * mel[t * NMELS + m]);
        sA[0][m] = 0.0f; sB[0][m] = M;
    } else {
        float B = 0.0f;
        for (int t = t0; t < t1; t++)
            B = fmaf(a1c, B, s0 * mel[t * NMELS + m]);
        sA[c][m] = __powf(a1c, (float)(t1 - t0));
        sB[c][m] = B;
    }
    __syncthreads();

    if (tid < NMELS) {
        float e0 = sB[0][tid];
        float e1 = fmaf(sA[1][tid], e0, sB[1][tid]);
        float e2 = fmaf(sA[2][tid], e1, sB[2][tid]);
        sMin[0][tid] = 0.0f;
        sMin[1][tid] = e0;
        sMin[2][tid] = e1;
        sMin[3][tid] = e2;
    }
    __syncthreads();

    float M = sMin[c][m];
    float sum = 0.0f, cs = 0.0f, sq = 0.0f, cq = 0.0f;
    for (int t = t0; t < t1; t++) {
        float xv = mel[t * NMELS + m];
        M = (c == 0 && t == 0) ? xv : fmaf(a1c, M, s0 * xv);
        float z = 1e-6f + M;
        float u = fmaf(xv, __powf(z, -0.98f), 2.0f);
        float p = u * rsqrtf(u) - sqrt2;
        obase[m * NFRAMES + t] = p;
        float y = p - cs, tn = sum + y; cs = (tn - sum) - y; sum = tn;
        float pp = p * p;
        float y2 = pp - cq, tq = sq + y2; cq = (tq - sq) - y2; sq = tq;
    }

    __shared__ double dsum[512];
    __shared__ double dsq[512];
    __shared__ float  s_mean, s_inv;
    dsum[tid] = (double)sum + (double)cs;
    dsq[tid]  = (double)sq  + (double)cq;
    __syncthreads();
    for (int o = 256; o > 0; o >>= 1) {
        if (tid < o) { dsum[tid] += dsum[tid + o]; dsq[tid] += dsq[tid + o]; }
        __syncthreads();
    }
    if (tid == 0) {
        const double n = (double)(NMELS * NFRAMES);
        double mean = dsum[0] / n;
        double var  = (dsq[0] - dsum[0] * dsum[0] / n) / (n - 1.0);
        if (var < 0.0) var = 0.0;
        s_mean = (float)mean;
        s_inv  = (float)(1.0 / (sqrt(var) + 1e-6));
    }
    __syncthreads();

    float mean = s_mean, inv = s_inv;
    float4* o4 = (float4*)obase;
    const int tot4 = NMELS * NFRAMES / 4;
    for (int i = tid; i < tot4; i += 512) {
        float4 v = o4[i];
        v.x = (v.x - mean) * inv;
        v.y = (v.y - mean) * inv;
        v.z = (v.z - mean) * inv;
        v.w = (v.w - mean) * inv;
        o4[i] = v;
    }
}

// ---------------- launch ------------------------------------------------------
extern "C" void kernel_launch(void* const* d_in, const int* in_sizes, int n_in,
                              void* d_out, int out_size) {
    const float* x = (const float*)d_in[0];
    float* out = (float*)d_out;

    init_kernel<<<NMELS + 8, 544>>>();
    melspec_kernel<<<dim3((NFRAMES + 3) / 4, BATCH), 128>>>(x);
    pcen_kernel<<<BATCH, 512>>>(out);
}